// round 3
// baseline (speedup 1.0000x reference)
#include <cuda_runtime.h>
#include <math.h>

// Problem constants
#define CIN   256      // channels
#define CH    128      // half channels (symmetry)
#define HW    16384    // 128*128 spatial
#define KC    32       // k-chunk per smem stage
#define TS    64       // spatial tile per block

// Cosine matrices, [j][n] layout, j = half-k index (0..127), n = 0..127
// Ae[j][n] = coeff for k=2j   : (j==0 ? 1 : 2cos(pi*2j*(2n+1)/512))
// Ao[j][n] = coeff for k=2j+1 :            2cos(pi*(2j+1)*(2n+1)/512)
__device__ float g_Ae[CH * CH];
__device__ float g_Ao[CH * CH];

__global__ void init_coeffs() {
    int idx = blockIdx.x * blockDim.x + threadIdx.x;   // 0..16383
    int j = idx >> 7;
    int n = idx & 127;
    // cospif does exact pi-fraction reduction; k*(2n+1) < 2^24 so numerator exact in fp32
    float t = (float)(2 * n + 1);
    float ae = (j == 0) ? 1.0f
                        : 2.0f * cospif((float)(2 * j) * t * (1.0f / 512.0f));
    float ao = 2.0f * cospif((float)(2 * j + 1) * t * (1.0f / 512.0f));
    g_Ae[idx] = ae;
    g_Ao[idx] = ao;
}

// Block computes the full 256 output channels for a TS=64-wide spatial tile of one batch.
// 256 threads: tn = tid/16 selects 8 n-rows (tn*8..tn*8+7), ts = tid%16 selects 4 spatial cols.
// Each thread keeps 8x4 E-accumulators and 8x4 O-accumulators.
__global__ __launch_bounds__(256) void idct_gemm(const float* __restrict__ ip,
                                                 float* __restrict__ out) {
    const int b  = blockIdx.x >> 8;     // 256 spatial tiles per batch image
    const int st = blockIdx.x & 255;
    const int s0 = st * TS;

    __shared__ float sAe[KC][CH];   // 16 KB
    __shared__ float sAo[KC][CH];   // 16 KB
    __shared__ float sXe[KC][TS];   //  8 KB
    __shared__ float sXo[KC][TS];   //  8 KB   -> 48 KB total

    const int tid = threadIdx.x;
    const int tn  = tid >> 4;       // 0..15
    const int ts  = tid & 15;       // 0..15

    const float* xbase = ip + (size_t)b * CIN * HW + s0;

    float accE[8][4];
    float accO[8][4];
#pragma unroll
    for (int i = 0; i < 8; i++)
#pragma unroll
        for (int j = 0; j < 4; j++) { accE[i][j] = 0.0f; accO[i][j] = 0.0f; }

    for (int kc = 0; kc < CH; kc += KC) {
        // Stage A chunks: KC x 128 floats = 1024 float4 each -> 4 per thread
#pragma unroll
        for (int r = 0; r < 4; r++) {
            int f4  = tid + r * 256;          // 0..1023
            int row = f4 >> 5;                // /32
            int col = (f4 & 31) << 2;
            *(float4*)&sAe[row][col] = *(const float4*)&g_Ae[(kc + row) * CH + col];
            *(float4*)&sAo[row][col] = *(const float4*)&g_Ao[(kc + row) * CH + col];
        }
        // Stage X chunks: KC x 64 floats = 512 float4 each -> 2 per thread
#pragma unroll
        for (int r = 0; r < 2; r++) {
            int f4  = tid + r * 256;          // 0..511
            int row = f4 >> 4;
            int col = (f4 & 15) << 2;
            *(float4*)&sXe[row][col] =
                *(const float4*)&xbase[(size_t)(2 * (kc + row)) * HW + col];
            *(float4*)&sXo[row][col] =
                *(const float4*)&xbase[(size_t)(2 * (kc + row) + 1) * HW + col];
        }
        __syncthreads();

#pragma unroll 8
        for (int k = 0; k < KC; k++) {
            float4 a0 = *(float4*)&sAe[k][tn * 8];
            float4 a1 = *(float4*)&sAe[k][tn * 8 + 4];
            float4 o0 = *(float4*)&sAo[k][tn * 8];
            float4 o1 = *(float4*)&sAo[k][tn * 8 + 4];
            float4 xe4 = *(float4*)&sXe[k][ts * 4];
            float4 xo4 = *(float4*)&sXo[k][ts * 4];
            float ae[8] = {a0.x, a0.y, a0.z, a0.w, a1.x, a1.y, a1.z, a1.w};
            float ao[8] = {o0.x, o0.y, o0.z, o0.w, o1.x, o1.y, o1.z, o1.w};
            float xe[4] = {xe4.x, xe4.y, xe4.z, xe4.w};
            float xo[4] = {xo4.x, xo4.y, xo4.z, xo4.w};
#pragma unroll
            for (int i = 0; i < 8; i++) {
#pragma unroll
                for (int j = 0; j < 4; j++) {
                    accE[i][j] = fmaf(ae[i], xe[j], accE[i][j]);
                    accO[i][j] = fmaf(ao[i], xo[j], accO[i][j]);
                }
            }
        }
        __syncthreads();
    }

    // Epilogue: out[n] = E+O, out[255-n] = E-O
    float* obase = out + (size_t)b * CIN * HW + s0 + ts * 4;
#pragma unroll
    for (int i = 0; i < 8; i++) {
        int n = tn * 8 + i;
        float4 top, bot;
        top.x = accE[i][0] + accO[i][0];  bot.x = accE[i][0] - accO[i][0];
        top.y = accE[i][1] + accO[i][1];  bot.y = accE[i][1] - accO[i][1];
        top.z = accE[i][2] + accO[i][2];  bot.z = accE[i][2] - accO[i][2];
        top.w = accE[i][3] + accO[i][3];  bot.w = accE[i][3] - accO[i][3];
        *(float4*)&obase[(size_t)n * HW]         = top;
        *(float4*)&obase[(size_t)(255 - n) * HW] = bot;
    }
}

extern "C" void kernel_launch(void* const* d_in, const int* in_sizes, int n_in,
                              void* d_out, int out_size) {
    const float* ip = (const float*)d_in[0];
    float* out = (float*)d_out;
    (void)in_sizes; (void)n_in; (void)out_size;

    init_coeffs<<<64, 256>>>();          // 16384 threads, fills both 128x128 matrices
    idct_gemm<<<8 * 256, 256>>>(ip, out);
}

// round 7
// speedup vs baseline: 1.8855x; 1.8855x over previous
#include <cuda_runtime.h>
#include <math.h>

#define HW 16384     // 128*128 spatial
#define TS 64        // spatial tile per block

// Level-2 cosine matrices, [i][n] layout, i = k-index 0..63, n = 0..63
// Me[i][n] = (i==0 ? 1 : 2cos(pi*i*(2n+1)/128))       (even-j half of size-128 DCT-III)
// Mo[i][n] =           2cos(pi*(2i+1)*(2n+1)/256)     (odd-j half)
__device__ float g_Me[64 * 64];
__device__ float g_Mo[64 * 64];

__global__ void init_coeffs() {
    int idx = blockIdx.x * 256 + threadIdx.x;   // 0..4095  (16 blocks x 256)
    int i = idx >> 6;                            // 0..63
    int n = idx & 63;                            // 0..63
    float t = (float)(2 * n + 1);
    g_Me[idx] = (i == 0) ? 1.0f
                         : 2.0f * cospif((float)i * t * (1.0f / 128.0f));
    g_Mo[idx] = 2.0f * cospif((float)(2 * i + 1) * t * (1.0f / 256.0f));
}

// Block: full 256 output channels for a TS=64 spatial tile of one batch image.
// 256 threads: tn=tid/16 -> 4 n-rows (n in [0,64)), ts=tid%16 -> 4 spatial cols.
// Four 64x64 GEMMs: PE=Me*xee, QE=Mo*xeo, PH=Me*he, QH=Mo*ho, where
//   xee[i]=x[4i], xeo[i]=x[4i+2], he[i]=x[4i+1]+x[4i-1] (he[0]=x[1]), ho[i]=x[4i+3]+x[4i+1]
// Combine (n in [0,64)):
//   E[n]=PE+QE, E[127-n]=PE-QE;  F[n]=PH+QH, F[127-n]=PH-QH
//   O[m]=(F[m]+h[0])*sec[m],  sec[m]=0.5/cos(pi*(2m+1)/512)
//   out[m]=E[m]+O[m], out[255-m]=E[m]-O[m]
__global__ __launch_bounds__(256, 2) void idct_lee(const float* __restrict__ ip,
                                                   float* __restrict__ out) {
    extern __shared__ float sm[];
    float* sMe  = sm;            // 4096 floats
    float* sMo  = sm + 4096;
    float* sXee = sm + 8192;     // [i][s] 64x64
    float* sXeo = sm + 12288;
    float* sHe  = sm + 16384;
    float* sHo  = sm + 20480;    // total 24576 floats = 96 KB

    const int b  = blockIdx.x >> 8;
    const int st = blockIdx.x & 255;
    const int s0 = st * TS;
    const int tid = threadIdx.x;
    const int tn = tid >> 4;     // 0..15
    const int ts = tid & 15;     // 0..15

    const float* xb = ip + (size_t)b * 256 * HW + s0;

    // ---- stage cosine matrices: 2048 float4, 8 per thread ----
#pragma unroll
    for (int r = 0; r < 4; r++) {
        int off = (tid + r * 256) << 2;            // float offset 0..4092
        *(float4*)&sMe[off] = *(const float4*)&g_Me[off];
        *(float4*)&sMo[off] = *(const float4*)&g_Mo[off];
    }

    // ---- stage input tiles: each buffer 64x64 floats = 1024 float4 ----
#pragma unroll
    for (int r = 0; r < 4; r++) {
        int f4 = tid + r * 256;                    // 0..1023
        int i  = f4 >> 4;                          // 0..63
        int sc = (f4 & 15) << 2;                   // 0..60

        float4 xee = *(const float4*)&xb[(size_t)(4 * i) * HW + sc];
        float4 xeo = *(const float4*)&xb[(size_t)(4 * i + 2) * HW + sc];
        float4 a1  = *(const float4*)&xb[(size_t)(4 * i + 1) * HW + sc];
        float4 a3  = *(const float4*)&xb[(size_t)(4 * i + 3) * HW + sc];

        float4 he = a1;
        if (i > 0) {
            float4 am = *(const float4*)&xb[(size_t)(4 * i - 1) * HW + sc];
            he.x += am.x; he.y += am.y; he.z += am.z; he.w += am.w;
        }
        float4 ho;
        ho.x = a3.x + a1.x; ho.y = a3.y + a1.y;
        ho.z = a3.z + a1.z; ho.w = a3.w + a1.w;

        *(float4*)&sXee[i * 64 + sc] = xee;
        *(float4*)&sXeo[i * 64 + sc] = xeo;
        *(float4*)&sHe[i * 64 + sc]  = he;
        *(float4*)&sHo[i * 64 + sc]  = ho;
    }
    __syncthreads();

    float aPE[4][4], aQE[4][4], aPH[4][4], aQH[4][4];
#pragma unroll
    for (int i = 0; i < 4; i++)
#pragma unroll
        for (int j = 0; j < 4; j++) {
            aPE[i][j] = 0.0f; aQE[i][j] = 0.0f;
            aPH[i][j] = 0.0f; aQH[i][j] = 0.0f;
        }

    const int nOff = tn * 4;
    const int sOff = ts * 4;

#pragma unroll 8
    for (int k = 0; k < 64; k++) {
        float4 me4 = *(float4*)&sMe[k * 64 + nOff];
        float4 mo4 = *(float4*)&sMo[k * 64 + nOff];
        float4 xe4 = *(float4*)&sXee[k * 64 + sOff];
        float4 xo4 = *(float4*)&sXeo[k * 64 + sOff];
        float4 he4 = *(float4*)&sHe[k * 64 + sOff];
        float4 ho4 = *(float4*)&sHo[k * 64 + sOff];

        float me[4] = {me4.x, me4.y, me4.z, me4.w};
        float mo[4] = {mo4.x, mo4.y, mo4.z, mo4.w};
        float xe[4] = {xe4.x, xe4.y, xe4.z, xe4.w};
        float xo[4] = {xo4.x, xo4.y, xo4.z, xo4.w};
        float he[4] = {he4.x, he4.y, he4.z, he4.w};
        float ho[4] = {ho4.x, ho4.y, ho4.z, ho4.w};

#pragma unroll
        for (int i = 0; i < 4; i++) {
#pragma unroll
            for (int j = 0; j < 4; j++) {
                aPE[i][j] = fmaf(me[i], xe[j], aPE[i][j]);
                aQE[i][j] = fmaf(mo[i], xo[j], aQE[i][j]);
                aPH[i][j] = fmaf(me[i], he[j], aPH[i][j]);
                aQH[i][j] = fmaf(mo[i], ho[j], aQH[i][j]);
            }
        }
    }

    // ---- epilogue ----
    float4 h0f = *(float4*)&sHe[sOff];   // he[0][s] = x[1][s] = h[0]
    float h0[4] = {h0f.x, h0f.y, h0f.z, h0f.w};

    float* ob = out + (size_t)b * 256 * HW + s0 + sOff;

#pragma unroll
    for (int i = 0; i < 4; i++) {
        int n  = nOff + i;        // 0..63
        int nm = 127 - n;         // 64..127
        float secn = 0.5f / cospif((float)(2 * n + 1)  * (1.0f / 512.0f));
        float secm = 0.5f / cospif((float)(2 * nm + 1) * (1.0f / 512.0f));

        float4 rn, rnm, rn128, rn255;
        float* prn    = (float*)&rn;
        float* prnm   = (float*)&rnm;
        float* prn128 = (float*)&rn128;
        float* prn255 = (float*)&rn255;

#pragma unroll
        for (int j = 0; j < 4; j++) {
            float E  = aPE[i][j] + aQE[i][j];
            float Em = aPE[i][j] - aQE[i][j];
            float Hf = aPH[i][j] + aQH[i][j];
            float Hm = aPH[i][j] - aQH[i][j];
            float O  = (Hf + h0[j]) * secn;
            float Om = (Hm + h0[j]) * secm;
            prn[j]    = E + O;     // out[n]
            prn255[j] = E - O;     // out[255-n]
            prnm[j]   = Em + Om;   // out[127-n]
            prn128[j] = Em - Om;   // out[128+n]
        }
        *(float4*)&ob[(size_t)n * HW]         = rn;
        *(float4*)&ob[(size_t)nm * HW]        = rnm;
        *(float4*)&ob[(size_t)(128 + n) * HW] = rn128;
        *(float4*)&ob[(size_t)(255 - n) * HW] = rn255;
    }
}

extern "C" void kernel_launch(void* const* d_in, const int* in_sizes, int n_in,
                              void* d_out, int out_size) {
    const float* ip = (const float*)d_in[0];
    float* out = (float*)d_out;
    (void)in_sizes; (void)n_in; (void)out_size;

    cudaFuncSetAttribute(idct_lee, cudaFuncAttributeMaxDynamicSharedMemorySize,
                         96 * 1024);

    init_coeffs<<<16, 256>>>();    // exactly 4096 writes per 64x64 matrix
    idct_lee<<<8 * 256, 256, 96 * 1024>>>(ip, out);
}

// round 12
// speedup vs baseline: 2.4516x; 1.3002x over previous
#include <cuda_runtime.h>
#include <math.h>

#define HW 16384     // 128*128 spatial
#define TS 64        // spatial tile per block

// Innermost 32x32 matrices for the size-64 symmetric split, [i][n], i,n in [0,32)
// Me[i][n] = (i==0 ? 1 : 2cos(pi*i*(2n+1)/64))
// Mo[i][n] =            2cos(pi*(2i+1)*(2n+1)/128)
__device__ float g_Me[32 * 32];
__device__ float g_Mo[32 * 32];

__global__ void init_coeffs() {
    int idx = blockIdx.x * 256 + threadIdx.x;   // 0..1023 (4 blocks x 256)
    int i = idx >> 5;                            // 0..31
    int n = idx & 31;                            // 0..31
    float t = (float)(2 * n + 1);
    g_Me[idx] = (i == 0) ? 1.0f
                         : 2.0f * cospif((float)i * t * (1.0f / 64.0f));
    g_Mo[idx] = 2.0f * cospif((float)(2 * i + 1) * t * (1.0f / 128.0f));
}

// Level-3 Lee iDCT: 8 GEMMs of 32x32 per spatial column.
// Input buffers (i in [0,32), per column):
//   ue=x[8i], uo=x[8i+4], gue=x[8i+2]+x[8i-2], guo=x[8i+6]+x[8i+2],
//   pe=x[8i+1]+x[8i-1],   po=x[8i+5]+x[8i+3],
//   gpe=x[8i+3]+x[8i+1]+x[8i-1]+x[8i-3], gpo=x[8i+7]+x[8i+5]+x[8i+3]+x[8i+1]
// (negative indices = 0)
// GEMMs: PU=Me*ue, QU=Mo*uo, PGU=Me*gue, QGU=Mo*guo,
//        PP=Me*pe, QP=Mo*po, PGP=Me*gpe, QGP=Mo*gpo
// Stage1 (sym, N=64):  A[n]=P+Q, A[63-n]=P-Q  for the four transforms U,GU,P,GP
// Stage2 (Lee, N=128): q2 = (AGU[m]+gu0)*ic128[m]; E[m]=AU[m]+q2; E[127-m]=AU[m]-q2
//                      (same with AP/AGP/gp0 -> H)          ic128[m]=0.5/cos(pi(2m+1)/256)
// Stage3 (Lee, N=256): q3 = (H[m]+h0)*ic256[m]; out[m]=E[m]+q3; out[255-m]=E[m]-q3
//                      h0 = x[1]                            ic256[m]=0.5/cos(pi(2m+1)/512)
__global__ __launch_bounds__(256, 2) void idct_lee3(const float* __restrict__ ip,
                                                    float* __restrict__ out) {
    extern __shared__ float sm[];
    float* sMe  = sm;              // 1024 floats
    float* sMo  = sm + 1024;       // 1024
    float* sUe  = sm + 2048;       // each buffer [i][s] 32x64 = 2048 floats
    float* sUo  = sm + 4096;
    float* sGue = sm + 6144;
    float* sGuo = sm + 8192;
    float* sPe  = sm + 10240;
    float* sPo  = sm + 12288;
    float* sGpe = sm + 14336;
    float* sGpo = sm + 16384;      // total 18432 floats = 72 KB

    const int b  = blockIdx.x >> 8;
    const int st = blockIdx.x & 255;
    const int s0 = st * TS;
    const int tid = threadIdx.x;
    const int tn = tid >> 4;       // 0..15 -> 2 n-rows each (n in [0,32))
    const int ts = tid & 15;       // 0..15 -> 4 spatial cols

    const float* xb = ip + (size_t)b * 256 * HW + s0;

    // ---- stage cosine matrices: 256 float4 each, 1 per thread ----
    {
        int off = tid << 2;
        *(float4*)&sMe[off] = *(const float4*)&g_Me[off];
        *(float4*)&sMo[off] = *(const float4*)&g_Mo[off];
    }

    // ---- stage 8 input buffers: 512 float4 each, 2 rounds of 256 ----
#pragma unroll
    for (int r = 0; r < 2; r++) {
        int f4 = tid + r * 256;                 // 0..511
        int i  = f4 >> 4;                       // 0..31
        int sc = (f4 & 15) << 2;                // 0..60

        float4 c0 = *(const float4*)&xb[(size_t)(8 * i)     * HW + sc];
        float4 c1 = *(const float4*)&xb[(size_t)(8 * i + 1) * HW + sc];
        float4 c2 = *(const float4*)&xb[(size_t)(8 * i + 2) * HW + sc];
        float4 c3 = *(const float4*)&xb[(size_t)(8 * i + 3) * HW + sc];
        float4 c4 = *(const float4*)&xb[(size_t)(8 * i + 4) * HW + sc];
        float4 c5 = *(const float4*)&xb[(size_t)(8 * i + 5) * HW + sc];
        float4 c6 = *(const float4*)&xb[(size_t)(8 * i + 6) * HW + sc];
        float4 c7 = *(const float4*)&xb[(size_t)(8 * i + 7) * HW + sc];
        float4 m1 = make_float4(0.f, 0.f, 0.f, 0.f);
        float4 m2 = m1, m3 = m1;
        if (i > 0) {
            m1 = *(const float4*)&xb[(size_t)(8 * i - 1) * HW + sc];
            m2 = *(const float4*)&xb[(size_t)(8 * i - 2) * HW + sc];
            m3 = *(const float4*)&xb[(size_t)(8 * i - 3) * HW + sc];
        }

        int o = i * 64 + sc;
        *(float4*)&sUe[o] = c0;
        *(float4*)&sUo[o] = c4;
        float4 v;
        v.x = c2.x + m2.x; v.y = c2.y + m2.y; v.z = c2.z + m2.z; v.w = c2.w + m2.w;
        *(float4*)&sGue[o] = v;
        v.x = c6.x + c2.x; v.y = c6.y + c2.y; v.z = c6.z + c2.z; v.w = c6.w + c2.w;
        *(float4*)&sGuo[o] = v;
        v.x = c1.x + m1.x; v.y = c1.y + m1.y; v.z = c1.z + m1.z; v.w = c1.w + m1.w;
        *(float4*)&sPe[o] = v;
        v.x = c5.x + c3.x; v.y = c5.y + c3.y; v.z = c5.z + c3.z; v.w = c5.w + c3.w;
        *(float4*)&sPo[o] = v;
        v.x = (c3.x + c1.x) + (m1.x + m3.x);
        v.y = (c3.y + c1.y) + (m1.y + m3.y);
        v.z = (c3.z + c1.z) + (m1.z + m3.z);
        v.w = (c3.w + c1.w) + (m1.w + m3.w);
        *(float4*)&sGpe[o] = v;
        v.x = (c7.x + c5.x) + (c3.x + c1.x);
        v.y = (c7.y + c5.y) + (c3.y + c1.y);
        v.z = (c7.z + c5.z) + (c3.z + c1.z);
        v.w = (c7.w + c5.w) + (c3.w + c1.w);
        *(float4*)&sGpo[o] = v;
    }
    __syncthreads();

    float aPU[2][4], aQU[2][4], aPGU[2][4], aQGU[2][4];
    float aPP[2][4], aQP[2][4], aPGP[2][4], aQGP[2][4];
#pragma unroll
    for (int i = 0; i < 2; i++)
#pragma unroll
        for (int j = 0; j < 4; j++) {
            aPU[i][j] = 0.f; aQU[i][j] = 0.f; aPGU[i][j] = 0.f; aQGU[i][j] = 0.f;
            aPP[i][j] = 0.f; aQP[i][j] = 0.f; aPGP[i][j] = 0.f; aQGP[i][j] = 0.f;
        }

    const int nOff = tn * 2;
    const int sOff = ts * 4;

#pragma unroll 8
    for (int k = 0; k < 32; k++) {
        float2 me2 = *(float2*)&sMe[k * 32 + nOff];
        float2 mo2 = *(float2*)&sMo[k * 32 + nOff];
        float4 v_ue  = *(float4*)&sUe [k * 64 + sOff];
        float4 v_uo  = *(float4*)&sUo [k * 64 + sOff];
        float4 v_gue = *(float4*)&sGue[k * 64 + sOff];
        float4 v_guo = *(float4*)&sGuo[k * 64 + sOff];
        float4 v_pe  = *(float4*)&sPe [k * 64 + sOff];
        float4 v_po  = *(float4*)&sPo [k * 64 + sOff];
        float4 v_gpe = *(float4*)&sGpe[k * 64 + sOff];
        float4 v_gpo = *(float4*)&sGpo[k * 64 + sOff];

        float me[2] = {me2.x, me2.y};
        float mo[2] = {mo2.x, mo2.y};
        float ue[4]  = {v_ue.x,  v_ue.y,  v_ue.z,  v_ue.w};
        float uo[4]  = {v_uo.x,  v_uo.y,  v_uo.z,  v_uo.w};
        float gue[4] = {v_gue.x, v_gue.y, v_gue.z, v_gue.w};
        float guo[4] = {v_guo.x, v_guo.y, v_guo.z, v_guo.w};
        float pe[4]  = {v_pe.x,  v_pe.y,  v_pe.z,  v_pe.w};
        float po[4]  = {v_po.x,  v_po.y,  v_po.z,  v_po.w};
        float gpe[4] = {v_gpe.x, v_gpe.y, v_gpe.z, v_gpe.w};
        float gpo[4] = {v_gpo.x, v_gpo.y, v_gpo.z, v_gpo.w};

#pragma unroll
        for (int i = 0; i < 2; i++) {
#pragma unroll
            for (int j = 0; j < 4; j++) {
                aPU [i][j] = fmaf(me[i], ue[j],  aPU [i][j]);
                aQU [i][j] = fmaf(mo[i], uo[j],  aQU [i][j]);
                aPGU[i][j] = fmaf(me[i], gue[j], aPGU[i][j]);
                aQGU[i][j] = fmaf(mo[i], guo[j], aQGU[i][j]);
                aPP [i][j] = fmaf(me[i], pe[j],  aPP [i][j]);
                aQP [i][j] = fmaf(mo[i], po[j],  aQP [i][j]);
                aPGP[i][j] = fmaf(me[i], gpe[j], aPGP[i][j]);
                aQGP[i][j] = fmaf(mo[i], gpo[j], aQGP[i][j]);
            }
        }
    }

    // ---- epilogue ----
    float4 gu0f = *(float4*)&sGue[sOff];   // gu[0] = x[2]
    float4 gp0f = *(float4*)&sGpe[sOff];   // gp[0] = x[3]+x[1]
    float4 h0f  = *(float4*)&sPe[sOff];    // h[0]  = x[1]
    float gu0[4] = {gu0f.x, gu0f.y, gu0f.z, gu0f.w};
    float gp0[4] = {gp0f.x, gp0f.y, gp0f.z, gp0f.w};
    float h0[4]  = {h0f.x,  h0f.y,  h0f.z,  h0f.w};

    float* ob = out + (size_t)b * 256 * HW + s0 + sOff;

#pragma unroll
    for (int i = 0; i < 2; i++) {
        int n  = nOff + i;        // 0..31
        int na = n;               // stage-1 row a
        int nb = 63 - n;          // stage-1 row b
        float icA = 0.5f / cospif((float)(2 * na + 1) * (1.0f / 256.0f));
        float icB = 0.5f / cospif((float)(2 * nb + 1) * (1.0f / 256.0f));

        // the four stage-2 output rows and their ic256 factors
        int   m2r[4] = {na, 127 - na, nb, 127 - nb};   // = {n, 127-n, 63-n, 64+n}
        float ic3[4];
#pragma unroll
        for (int q = 0; q < 4; q++)
            ic3[q] = 0.5f / cospif((float)(2 * m2r[q] + 1) * (1.0f / 512.0f));

        float4 ro[4], rp[4];      // out[m2], out[255-m2]
        float* pro[4] = {(float*)&ro[0], (float*)&ro[1], (float*)&ro[2], (float*)&ro[3]};
        float* prp[4] = {(float*)&rp[0], (float*)&rp[1], (float*)&rp[2], (float*)&rp[3]};

#pragma unroll
        for (int j = 0; j < 4; j++) {
            // stage 1 (sym, N=64)
            float AUa  = aPU [i][j] + aQU [i][j],  AUb  = aPU [i][j] - aQU [i][j];
            float AGUa = aPGU[i][j] + aQGU[i][j],  AGUb = aPGU[i][j] - aQGU[i][j];
            float APa  = aPP [i][j] + aQP [i][j],  APb  = aPP [i][j] - aQP [i][j];
            float AGPa = aPGP[i][j] + aQGP[i][j],  AGPb = aPGP[i][j] - aQGP[i][j];

            // stage 2 (Lee, N=128): rows {na, 127-na} from a; {nb, 127-nb} from b
            float q2ea = (AGUa + gu0[j]) * icA;
            float q2eb = (AGUb + gu0[j]) * icB;
            float q2ha = (AGPa + gp0[j]) * icA;
            float q2hb = (AGPb + gp0[j]) * icB;
            float E[4], Hh[4];
            E[0]  = AUa + q2ea;  E[1]  = AUa - q2ea;    // rows na, 127-na
            E[2]  = AUb + q2eb;  E[3]  = AUb - q2eb;    // rows nb, 127-nb
            Hh[0] = APa + q2ha;  Hh[1] = APa - q2ha;
            Hh[2] = APb + q2hb;  Hh[3] = APb - q2hb;

            // stage 3 (Lee, N=256)
#pragma unroll
            for (int q = 0; q < 4; q++) {
                float q3 = (Hh[q] + h0[j]) * ic3[q];
                pro[q][j] = E[q] + q3;      // out[m2]
                prp[q][j] = E[q] - q3;      // out[255-m2]
            }
        }

#pragma unroll
        for (int q = 0; q < 4; q++) {
            *(float4*)&ob[(size_t)m2r[q] * HW]         = ro[q];
            *(float4*)&ob[(size_t)(255 - m2r[q]) * HW] = rp[q];
        }
    }
}

extern "C" void kernel_launch(void* const* d_in, const int* in_sizes, int n_in,
                              void* d_out, int out_size) {
    const float* ip = (const float*)d_in[0];
    float* out = (float*)d_out;
    (void)in_sizes; (void)n_in; (void)out_size;

    cudaFuncSetAttribute(idct_lee3, cudaFuncAttributeMaxDynamicSharedMemorySize,
                         72 * 1024);

    init_coeffs<<<4, 256>>>();     // exactly 1024 writes per 32x32 matrix
    idct_lee3<<<8 * 256, 256, 72 * 1024>>>(ip, out);
}

// round 13
// speedup vs baseline: 2.4605x; 1.0036x over previous
#include <cuda_runtime.h>
#include <math.h>

#define HW 16384     // 128*128 spatial
#define TS 64        // spatial tile per block

// Innermost 32x32 matrices for the size-64 symmetric split, [i][n], i,n in [0,32)
__device__ float g_Me[32 * 32];
__device__ float g_Mo[32 * 32];

__global__ void init_coeffs() {
    int idx = blockIdx.x * 256 + threadIdx.x;   // 0..1023 (4 blocks x 256)
    int i = idx >> 5;
    int n = idx & 31;
    float t = (float)(2 * n + 1);
    g_Me[idx] = (i == 0) ? 1.0f
                         : 2.0f * cospif((float)i * t * (1.0f / 64.0f));
    g_Mo[idx] = 2.0f * cospif((float)(2 * i + 1) * t * (1.0f / 128.0f));
}

// Level-3 Lee iDCT, 4x4 micro-tile, 128 threads/CTA.
// Same math as R12: 8 GEMMs of 32x32 per spatial column, 3 combine stages.
__global__ __launch_bounds__(128, 2) void idct_lee3(const float* __restrict__ ip,
                                                    float* __restrict__ out) {
    extern __shared__ float sm[];
    float* sMe  = sm;              // 1024 floats
    float* sMo  = sm + 1024;       // 1024
    float* sUe  = sm + 2048;       // each buffer [i][s] 32x64 = 2048 floats
    float* sUo  = sm + 4096;
    float* sGue = sm + 6144;
    float* sGuo = sm + 8192;
    float* sPe  = sm + 10240;
    float* sPo  = sm + 12288;
    float* sGpe = sm + 14336;
    float* sGpo = sm + 16384;      // total 18432 floats = 72 KB

    const int b  = blockIdx.x >> 8;
    const int st = blockIdx.x & 255;
    const int s0 = st * TS;
    const int tid = threadIdx.x;
    const int tn = tid >> 4;       // 0..7  -> 4 n-rows each (n in [0,32))
    const int ts = tid & 15;       // 0..15 -> 4 spatial cols

    const float* xb = ip + (size_t)b * 256 * HW + s0;

    // ---- stage cosine matrices: 256 float4 each, 2 per thread ----
#pragma unroll
    for (int r = 0; r < 2; r++) {
        int off = (tid + r * 128) << 2;
        *(float4*)&sMe[off] = *(const float4*)&g_Me[off];
        *(float4*)&sMo[off] = *(const float4*)&g_Mo[off];
    }

    // ---- stage 8 input buffers: 512 float4 each, 4 rounds of 128 ----
#pragma unroll
    for (int r = 0; r < 4; r++) {
        int f4 = tid + r * 128;                 // 0..511
        int i  = f4 >> 4;                       // 0..31
        int sc = (f4 & 15) << 2;                // 0..60

        float4 c0 = *(const float4*)&xb[(size_t)(8 * i)     * HW + sc];
        float4 c1 = *(const float4*)&xb[(size_t)(8 * i + 1) * HW + sc];
        float4 c2 = *(const float4*)&xb[(size_t)(8 * i + 2) * HW + sc];
        float4 c3 = *(const float4*)&xb[(size_t)(8 * i + 3) * HW + sc];
        float4 c4 = *(const float4*)&xb[(size_t)(8 * i + 4) * HW + sc];
        float4 c5 = *(const float4*)&xb[(size_t)(8 * i + 5) * HW + sc];
        float4 c6 = *(const float4*)&xb[(size_t)(8 * i + 6) * HW + sc];
        float4 c7 = *(const float4*)&xb[(size_t)(8 * i + 7) * HW + sc];
        float4 m1 = make_float4(0.f, 0.f, 0.f, 0.f);
        float4 m2 = m1, m3 = m1;
        if (i > 0) {
            m1 = *(const float4*)&xb[(size_t)(8 * i - 1) * HW + sc];
            m2 = *(const float4*)&xb[(size_t)(8 * i - 2) * HW + sc];
            m3 = *(const float4*)&xb[(size_t)(8 * i - 3) * HW + sc];
        }

        int o = i * 64 + sc;
        *(float4*)&sUe[o] = c0;
        *(float4*)&sUo[o] = c4;
        float4 v;
        v.x = c2.x + m2.x; v.y = c2.y + m2.y; v.z = c2.z + m2.z; v.w = c2.w + m2.w;
        *(float4*)&sGue[o] = v;
        v.x = c6.x + c2.x; v.y = c6.y + c2.y; v.z = c6.z + c2.z; v.w = c6.w + c2.w;
        *(float4*)&sGuo[o] = v;
        v.x = c1.x + m1.x; v.y = c1.y + m1.y; v.z = c1.z + m1.z; v.w = c1.w + m1.w;
        *(float4*)&sPe[o] = v;
        v.x = c5.x + c3.x; v.y = c5.y + c3.y; v.z = c5.z + c3.z; v.w = c5.w + c3.w;
        *(float4*)&sPo[o] = v;
        v.x = (c3.x + c1.x) + (m1.x + m3.x);
        v.y = (c3.y + c1.y) + (m1.y + m3.y);
        v.z = (c3.z + c1.z) + (m1.z + m3.z);
        v.w = (c3.w + c1.w) + (m1.w + m3.w);
        *(float4*)&sGpe[o] = v;
        v.x = (c7.x + c5.x) + (c3.x + c1.x);
        v.y = (c7.y + c5.y) + (c3.y + c1.y);
        v.z = (c7.z + c5.z) + (c3.z + c1.z);
        v.w = (c7.w + c5.w) + (c3.w + c1.w);
        *(float4*)&sGpo[o] = v;
    }
    __syncthreads();

    float aPU[4][4], aQU[4][4], aPGU[4][4], aQGU[4][4];
    float aPP[4][4], aQP[4][4], aPGP[4][4], aQGP[4][4];
#pragma unroll
    for (int i = 0; i < 4; i++)
#pragma unroll
        for (int j = 0; j < 4; j++) {
            aPU[i][j] = 0.f; aQU[i][j] = 0.f; aPGU[i][j] = 0.f; aQGU[i][j] = 0.f;
            aPP[i][j] = 0.f; aQP[i][j] = 0.f; aPGP[i][j] = 0.f; aQGP[i][j] = 0.f;
        }

    const int nOff = tn * 4;
    const int sOff = ts * 4;

#pragma unroll 2
    for (int k = 0; k < 32; k++) {
        float4 me4 = *(float4*)&sMe[k * 32 + nOff];
        float4 mo4 = *(float4*)&sMo[k * 32 + nOff];
        float4 v_ue  = *(float4*)&sUe [k * 64 + sOff];
        float4 v_uo  = *(float4*)&sUo [k * 64 + sOff];
        float4 v_gue = *(float4*)&sGue[k * 64 + sOff];
        float4 v_guo = *(float4*)&sGuo[k * 64 + sOff];
        float4 v_pe  = *(float4*)&sPe [k * 64 + sOff];
        float4 v_po  = *(float4*)&sPo [k * 64 + sOff];
        float4 v_gpe = *(float4*)&sGpe[k * 64 + sOff];
        float4 v_gpo = *(float4*)&sGpo[k * 64 + sOff];

        float me[4] = {me4.x, me4.y, me4.z, me4.w};
        float mo[4] = {mo4.x, mo4.y, mo4.z, mo4.w};
        float ue[4]  = {v_ue.x,  v_ue.y,  v_ue.z,  v_ue.w};
        float uo[4]  = {v_uo.x,  v_uo.y,  v_uo.z,  v_uo.w};
        float gue[4] = {v_gue.x, v_gue.y, v_gue.z, v_gue.w};
        float guo[4] = {v_guo.x, v_guo.y, v_guo.z, v_guo.w};
        float pe[4]  = {v_pe.x,  v_pe.y,  v_pe.z,  v_pe.w};
        float po[4]  = {v_po.x,  v_po.y,  v_po.z,  v_po.w};
        float gpe[4] = {v_gpe.x, v_gpe.y, v_gpe.z, v_gpe.w};
        float gpo[4] = {v_gpo.x, v_gpo.y, v_gpo.z, v_gpo.w};

#pragma unroll
        for (int i = 0; i < 4; i++) {
#pragma unroll
            for (int j = 0; j < 4; j++) {
                aPU [i][j] = fmaf(me[i], ue[j],  aPU [i][j]);
                aQU [i][j] = fmaf(mo[i], uo[j],  aQU [i][j]);
                aPGU[i][j] = fmaf(me[i], gue[j], aPGU[i][j]);
                aQGU[i][j] = fmaf(mo[i], guo[j], aQGU[i][j]);
                aPP [i][j] = fmaf(me[i], pe[j],  aPP [i][j]);
                aQP [i][j] = fmaf(mo[i], po[j],  aQP [i][j]);
                aPGP[i][j] = fmaf(me[i], gpe[j], aPGP[i][j]);
                aQGP[i][j] = fmaf(mo[i], gpo[j], aQGP[i][j]);
            }
        }
    }

    // ---- epilogue ----
    float4 gu0f = *(float4*)&sGue[sOff];   // gu[0] = x[2]
    float4 gp0f = *(float4*)&sGpe[sOff];   // gp[0] = x[3]+x[1]
    float4 h0f  = *(float4*)&sPe[sOff];    // h[0]  = x[1]
    float gu0[4] = {gu0f.x, gu0f.y, gu0f.z, gu0f.w};
    float gp0[4] = {gp0f.x, gp0f.y, gp0f.z, gp0f.w};
    float h0[4]  = {h0f.x,  h0f.y,  h0f.z,  h0f.w};

    float* ob = out + (size_t)b * 256 * HW + s0 + sOff;

#pragma unroll
    for (int i = 0; i < 4; i++) {
        int n  = nOff + i;        // 0..31
        int na = n;
        int nb = 63 - n;
        float icA = 0.5f / cospif((float)(2 * na + 1) * (1.0f / 256.0f));
        float icB = 0.5f / cospif((float)(2 * nb + 1) * (1.0f / 256.0f));

        int   m2r[4] = {na, 127 - na, nb, 127 - nb};
        float ic3[4];
#pragma unroll
        for (int q = 0; q < 4; q++)
            ic3[q] = 0.5f / cospif((float)(2 * m2r[q] + 1) * (1.0f / 512.0f));

        float4 ro[4], rp[4];
        float* pro[4] = {(float*)&ro[0], (float*)&ro[1], (float*)&ro[2], (float*)&ro[3]};
        float* prp[4] = {(float*)&rp[0], (float*)&rp[1], (float*)&rp[2], (float*)&rp[3]};

#pragma unroll
        for (int j = 0; j < 4; j++) {
            float AUa  = aPU [i][j] + aQU [i][j],  AUb  = aPU [i][j] - aQU [i][j];
            float AGUa = aPGU[i][j] + aQGU[i][j],  AGUb = aPGU[i][j] - aQGU[i][j];
            float APa  = aPP [i][j] + aQP [i][j],  APb  = aPP [i][j] - aQP [i][j];
            float AGPa = aPGP[i][j] + aQGP[i][j],  AGPb = aPGP[i][j] - aQGP[i][j];

            float q2ea = (AGUa + gu0[j]) * icA;
            float q2eb = (AGUb + gu0[j]) * icB;
            float q2ha = (AGPa + gp0[j]) * icA;
            float q2hb = (AGPb + gp0[j]) * icB;
            float E[4], Hh[4];
            E[0]  = AUa + q2ea;  E[1]  = AUa - q2ea;
            E[2]  = AUb + q2eb;  E[3]  = AUb - q2eb;
            Hh[0] = APa + q2ha;  Hh[1] = APa - q2ha;
            Hh[2] = APb + q2hb;  Hh[3] = APb - q2hb;

#pragma unroll
            for (int q = 0; q < 4; q++) {
                float q3 = (Hh[q] + h0[j]) * ic3[q];
                pro[q][j] = E[q] + q3;
                prp[q][j] = E[q] - q3;
            }
        }

#pragma unroll
        for (int q = 0; q < 4; q++) {
            *(float4*)&ob[(size_t)m2r[q] * HW]         = ro[q];
            *(float4*)&ob[(size_t)(255 - m2r[q]) * HW] = rp[q];
        }
    }
}

extern "C" void kernel_launch(void* const* d_in, const int* in_sizes, int n_in,
                              void* d_out, int out_size) {
    const float* ip = (const float*)d_in[0];
    float* out = (float*)d_out;
    (void)in_sizes; (void)n_in; (void)out_size;

    cudaFuncSetAttribute(idct_lee3, cudaFuncAttributeMaxDynamicSharedMemorySize,
                         72 * 1024);

    init_coeffs<<<4, 256>>>();
    idct_lee3<<<8 * 256, 128, 72 * 1024>>>(ip, out);
}